// round 11
// baseline (speedup 1.0000x reference)
#include <cuda_runtime.h>
#include <cstdint>

// Problem constants (fixed shapes from reference)
#define NQc 8192
#define NKc 8192
#define Dc  512

__device__ __align__(16) float g_Qp[(size_t)NQc * Dc];
__device__ __align__(16) float g_Kp[(size_t)NKc * Dc];
__device__ __align__(16) float g_Vt[(size_t)Dc * NKc];
__device__ __align__(16) float g_S [(size_t)NQc * NKc];

static constexpr float SCALE_P = 0.044194173824159216f; // 1/sqrt(512)
static constexpr float NEGV    = -4294967296.0f;        // -(1<<32)

enum { EPI_NONE = 0, EPI_BIAS = 1, EPI_MASK = 2 };

// fp32 -> tf32 (round-to-nearest) kept in a 32-bit container (low 13 bits zero)
__device__ __forceinline__ uint32_t f2tf(float f) {
    uint32_t r;
    asm("cvt.rna.tf32.f32 %0, %1;" : "=r"(r) : "f"(f));
    return r;
}
__device__ __forceinline__ float f2tf_f(float f) { return __uint_as_float(f2tf(f)); }

__device__ __forceinline__ uint32_t smem_u32(const void* p) {
    uint32_t r;
    asm("{ .reg .u64 t; cvta.to.shared.u64 t, %1; cvt.u32.u64 %0, t; }"
        : "=r"(r) : "l"(p));
    return r;
}

#define CP_ASYNC16(dst, src) \
    asm volatile("cp.async.cg.shared.global [%0], [%1], 16;" \
                 :: "r"(dst), "l"(src) : "memory")
#define CP_COMMIT() asm volatile("cp.async.commit_group;" ::: "memory")
#define CP_WAIT(N)  asm volatile("cp.async.wait_group %0;" :: "n"(N) : "memory")

#define LDSM_X4(r, addr) \
    asm volatile("ldmatrix.sync.aligned.m8n8.x4.shared.b16 {%0,%1,%2,%3}, [%4];" \
                 : "=r"((r)[0]), "=r"((r)[1]), "=r"((r)[2]), "=r"((r)[3]) \
                 : "r"(addr))

__device__ __forceinline__ void mma8(float* c, const uint32_t* a, const uint32_t* b) {
    asm volatile(
        "mma.sync.aligned.m16n8k8.row.col.f32.tf32.tf32.f32 "
        "{%0,%1,%2,%3}, {%4,%5,%6,%7}, {%8,%9}, {%0,%1,%2,%3};"
        : "+f"(c[0]), "+f"(c[1]), "+f"(c[2]), "+f"(c[3])
        : "r"(a[0]), "r"(a[1]), "r"(a[2]), "r"(a[3]), "r"(b[0]), "r"(b[1]));
}

// ---------------------------------------------------------------- mma GEMM
// C[M,N] = A[M,K] @ B^T, A:[M,K], B:[N,K], all K-major.
// BM=128, BN=256, BK=32; 256 threads = 8 warps (2 M x 4 N), warp tile 64x64.
// 1 CTA/SM (acc = 128 regs). 3-stage cp.async pipeline, ONE barrier per chunk.
// Smem tiles [row][32] with XOR swizzle on the float4 column
// (col4' = col4 ^ (row&7)); all fragments via ldmatrix.x4.
// If blockIdx.z == 1, the second operand set (A2/B2/C2/bias2) is used
// (lets both projections run as a single launch).
// NOTE: MMA reads raw fp32 bits as tf32 (truncation). For exact tf32 math,
// A/B must be pre-rounded to tf32 in gmem (true for Qp, Kp, P, Vt).
// Requires M%128==0, N%256==0, KC=K/32>=2.
template <int EPI>
__global__ void __launch_bounds__(256, 1)
mma_gemm(const float* __restrict__ A, const float* __restrict__ B,
         float* __restrict__ C, const float* __restrict__ bias,
         const int* __restrict__ mask,
         const float* __restrict__ A2, const float* __restrict__ B2,
         float* __restrict__ C2, const float* __restrict__ bias2,
         int M, int N, int K)
{
    constexpr int BM = 128, BN = 256, BK = 32, STAGES = 3;
    constexpr int STAGE_F = (BM + BN) * BK;       // floats per stage (12288)
    constexpr int STAGE_B = STAGE_F * 4;          // bytes (49152)
    constexpr int ABYTES  = BM * BK * 4;          // 16384

    if (blockIdx.z == 1) { A = A2; B = B2; C = C2; bias = bias2; }

    extern __shared__ float sm[];
    const uint32_t smb = smem_u32(sm);

    const int tid  = threadIdx.x;
    const int lane = tid & 31;
    const int wid  = tid >> 5;
    const int g    = lane >> 2;     // group id 0..7
    const int t    = lane & 3;      // thread-in-group 0..3

    const int m_warp = (wid & 1) * 64;   // 2 warps in M
    const int n_warp = (wid >> 1) * 64;  // 4 warps in N

    const int rowBase = blockIdx.y * BM;
    const int colBase = blockIdx.x * BN;

    // ---- ldmatrix per-lane addressing (x4: lane l -> matrix l>>3, row l&7)
    const int mat = lane >> 3;
    const int rim = lane & 7;
    const int km  = mat >> 1;
    const int kb  = mat & 1;
    // A fragment (mi, ks): row = m_warp + 16*mi + rim + 8*kb, col4 = 2*ks + km
    // B fragment (j,  ks): row = n_warp + 16*j  + rim + 8*km, col4 = 2*ks + kb
    const uint32_t aOff = (uint32_t)(m_warp + rim + 8 * kb) * (BK * 4);
    const uint32_t bOff = (uint32_t)ABYTES + (uint32_t)(n_warp + rim + 8 * km) * (BK * 4);

    // loader mapping: rows lr+32*it, float4 col lq, swizzled col sq
    const int lr = tid >> 3;        // 0..31
    const int lq = tid & 7;
    const int sq = lq ^ (lr & 7);

    const float* pa = A + (size_t)(rowBase + lr) * K + lq * 4;
    const float* pb = B + (size_t)(colBase + lr) * K + lq * 4;
    const uint32_t sa = smb + (uint32_t)(lr * BK + 4 * sq) * 4;
    const uint32_t sb = sa + (uint32_t)ABYTES;

    const int KC = K / BK;

    // issue one stage of cp.async (A: 4 x 16B, B: 8 x 16B per thread)
    auto issue = [&](int c, int s) {
        const float* qa = pa + (size_t)c * BK;
        const float* qb = pb + (size_t)c * BK;
        const uint32_t off = (uint32_t)s * STAGE_B;
#pragma unroll
        for (int it = 0; it < 4; it++)
            CP_ASYNC16(sa + off + (uint32_t)(32 * it * BK) * 4, qa + (size_t)(32 * it) * K);
#pragma unroll
        for (int it = 0; it < 8; it++)
            CP_ASYNC16(sb + off + (uint32_t)(32 * it * BK) * 4, qb + (size_t)(32 * it) * K);
        CP_COMMIT();
    };

    issue(0, 0);
    issue(1, 1);

    float acc[4][8][4];
#pragma unroll
    for (int i = 0; i < 4; i++)
#pragma unroll
        for (int j = 0; j < 8; j++)
#pragma unroll
            for (int r = 0; r < 4; r++) acc[i][j][r] = 0.0f;

    for (int c = 0; c < KC; c++) {
        if (c + 2 < KC) { CP_WAIT(1); } else { CP_WAIT(0); }
        __syncthreads();
        // all warps passed the barrier => reads of stage (c-1)%3 == (c+2)%3 done
        if (c + 2 < KC) issue(c + 2, (c + 2) % STAGES);

        const uint32_t stg = smb + (uint32_t)(c % STAGES) * STAGE_B;
#pragma unroll
        for (int ks = 0; ks < 4; ks++) {
            const uint32_t cA = 16u * (uint32_t)((2 * ks + km) ^ rim);
            const uint32_t cB = 16u * (uint32_t)((2 * ks + kb) ^ rim);
            uint32_t af[4][4];
#pragma unroll
            for (int mi = 0; mi < 4; mi++)
                LDSM_X4(af[mi], stg + aOff + (uint32_t)(mi * 16 * BK * 4) + cA);
            uint32_t bf[4][4];   // [j] = {b(n=16j,kLo), b(16j,kHi), b(16j+8,kLo), b(16j+8,kHi)}
#pragma unroll
            for (int j = 0; j < 4; j++)
                LDSM_X4(bf[j], stg + bOff + (uint32_t)(j * 16 * BK * 4) + cB);
#pragma unroll
            for (int mi = 0; mi < 4; mi++)
#pragma unroll
                for (int nj = 0; nj < 8; nj++)
                    mma8(acc[mi][nj], af[mi], &bf[nj >> 1][(nj & 1) * 2]);
        }
    }

    // ---- epilogue
    const int colW = colBase + n_warp;
#pragma unroll
    for (int mi = 0; mi < 4; mi++) {
        const int row0 = rowBase + m_warp + 16 * mi + g;
#pragma unroll
        for (int rr = 0; rr < 2; rr++) {
            const int row = row0 + 8 * rr;
            float* crow = C + (size_t)row * N;
            const int* mrow = (EPI == EPI_MASK) ? (mask + (size_t)row * N) : nullptr;
#pragma unroll
            for (int nj = 0; nj < 8; nj++) {
                const int col = colW + 8 * nj + 2 * t;
                float2 o = make_float2(acc[mi][nj][2 * rr], acc[mi][nj][2 * rr + 1]);
                if (EPI == EPI_BIAS) {
                    const float2 b = *(const float2*)(bias + col);
                    // round to tf32 so downstream cp.async GEMM is exact
                    o.x = f2tf_f(o.x + b.x);
                    o.y = f2tf_f(o.y + b.y);
                } else if (EPI == EPI_MASK) {
                    const int2 m = *(const int2*)(mrow + col);
                    o.x = m.x ? NEGV : o.x * SCALE_P;
                    o.y = m.y ? NEGV : o.y * SCALE_P;
                }
                *(float2*)(crow + col) = o;
            }
        }
    }
}

static constexpr int GEMM_SMEM = 3 * (128 + 256) * 32 * 4;  // 147456 bytes

// ---------------------------------------------------------------- V transpose
// Vt[d][n] = tf32_round(V[n][d]);  V:[NKc][Dc] -> Vt:[Dc][NKc]
__global__ __launch_bounds__(256)
void transpose_kernel(const float* __restrict__ V, float* __restrict__ Vt)
{
    __shared__ float tile[32][33];
    const int d0 = blockIdx.x * 32;
    const int n0 = blockIdx.y * 32;
    const int tx = threadIdx.x, ty = threadIdx.y;
#pragma unroll
    for (int j = 0; j < 32; j += 8)
        tile[ty + j][tx] = V[(size_t)(n0 + ty + j) * Dc + d0 + tx];
    __syncthreads();
#pragma unroll
    for (int j = 0; j < 32; j += 8)
        Vt[(size_t)(d0 + ty + j) * NKc + n0 + tx] = f2tf_f(tile[tx][ty + j]);
}

// ---------------------------------------------------------------- softmax
// In-place row softmax; stores tf32-rounded P so the P@V GEMM is exact.
__global__ __launch_bounds__(256)
void softmax_kernel(float* __restrict__ S)
{
    __shared__ float red[256];
    const int row = blockIdx.x;
    const int t = threadIdx.x;
    float* p = S + (size_t)row * NKc;

    float v[32];
    float mx = -3.4e38f;
#pragma unroll
    for (int i = 0; i < 32; i++) {
        v[i] = p[i * 256 + t];
        mx = fmaxf(mx, v[i]);
    }
    red[t] = mx;
    __syncthreads();
    for (int s = 128; s > 0; s >>= 1) {
        if (t < s) red[t] = fmaxf(red[t], red[t + s]);
        __syncthreads();
    }
    mx = red[0];
    __syncthreads();

    float sum = 0.0f;
#pragma unroll
    for (int i = 0; i < 32; i++) {
        v[i] = expf(v[i] - mx);
        sum += v[i];
    }
    red[t] = sum;
    __syncthreads();
    for (int s = 128; s > 0; s >>= 1) {
        if (t < s) red[t] += red[t + s];
        __syncthreads();
    }
    const float inv = 1.0f / red[0];
#pragma unroll
    for (int i = 0; i < 32; i++) p[i * 256 + t] = f2tf_f(v[i] * inv);
}

// ---------------------------------------------------------------- launcher
extern "C" void kernel_launch(void* const* d_in, const int* in_sizes, int n_in,
                              void* d_out, int out_size)
{
    (void)in_sizes; (void)n_in; (void)out_size;
    const float* Q    = (const float*)d_in[0];
    const float* K    = (const float*)d_in[1];
    const float* V    = (const float*)d_in[2];
    const float* WQw  = (const float*)d_in[3];
    const float* WQb  = (const float*)d_in[4];
    const float* WKw  = (const float*)d_in[5];
    const float* WKb  = (const float*)d_in[6];
    const int*   mask = (const int*)d_in[7];  // numpy bool -> int32 on device
    float* O = (float*)d_out;

    float *Qp, *Kp, *Vt, *S;
    cudaGetSymbolAddress((void**)&Qp, g_Qp);
    cudaGetSymbolAddress((void**)&Kp, g_Kp);
    cudaGetSymbolAddress((void**)&Vt, g_Vt);
    cudaGetSymbolAddress((void**)&S,  g_S);

    cudaFuncSetAttribute(mma_gemm<EPI_BIAS>,
                         cudaFuncAttributeMaxDynamicSharedMemorySize, GEMM_SMEM);
    cudaFuncSetAttribute(mma_gemm<EPI_MASK>,
                         cudaFuncAttributeMaxDynamicSharedMemorySize, GEMM_SMEM);
    cudaFuncSetAttribute(mma_gemm<EPI_NONE>,
                         cudaFuncAttributeMaxDynamicSharedMemorySize, GEMM_SMEM);

    const dim3 blk(256);

    // 0) Vt = tf32(V^T)   [512 x 8192]
    transpose_kernel<<<dim3(Dc / 32, NKc / 32), dim3(32, 8)>>>(V, Vt);

    // 1) Both projections in ONE launch (z=0: Q, z=1: K)   [8192 x 512]
    {
        dim3 grid(Dc / 256, NQc / 128, 2);
        mma_gemm<EPI_BIAS><<<grid, blk, GEMM_SMEM>>>(
            Q, WQw, Qp, WQb, nullptr,
            K, WKw, Kp, WKb, NQc, Dc, Dc);
    }
    // 2) S = mask ? NEG : (Qp @ Kp^T) * (1/sqrt(512))   [8192 x 8192]
    {
        dim3 grid(NKc / 256, NQc / 128, 1);
        mma_gemm<EPI_MASK><<<grid, blk, GEMM_SMEM>>>(
            Qp, Kp, S, nullptr, mask,
            nullptr, nullptr, nullptr, nullptr, NQc, NKc, Dc);
    }
    // 3) P = tf32(softmax_rows(S)), in place
    softmax_kernel<<<NQc, blk>>>(S);
    // 4) O = P @ V = P @ Vt^T   [8192 x 512]
    {
        dim3 grid(Dc / 256, NQc / 128, 1);
        mma_gemm<EPI_NONE><<<grid, blk, GEMM_SMEM>>>(
            S, Vt, O, nullptr, nullptr,
            nullptr, nullptr, nullptr, nullptr, NQc, Dc, NKc);
    }
}

// round 13
// speedup vs baseline: 1.7243x; 1.7243x over previous
#include <cuda_runtime.h>
#include <cstdint>

// Problem constants (fixed shapes from reference)
#define NQc 8192
#define NKc 8192
#define Dc  512

__device__ __align__(16) float g_Qp[(size_t)NQc * Dc];
__device__ __align__(16) float g_Kp[(size_t)NKc * Dc];
__device__ __align__(16) float g_Vt[(size_t)Dc * NKc];
__device__ __align__(16) float g_S [(size_t)NQc * NKc];

static constexpr float SCALE_P = 0.044194173824159216f; // 1/sqrt(512)
static constexpr float NEGV    = -4294967296.0f;        // -(1<<32)

enum { EPI_NONE = 0, EPI_BIAS = 1, EPI_MASK = 2 };

// fp32 -> tf32 (round-to-nearest) kept in a 32-bit container (low 13 bits zero)
__device__ __forceinline__ uint32_t f2tf(float f) {
    uint32_t r;
    asm("cvt.rna.tf32.f32 %0, %1;" : "=r"(r) : "f"(f));
    return r;
}
__device__ __forceinline__ float f2tf_f(float f) { return __uint_as_float(f2tf(f)); }

__device__ __forceinline__ uint32_t smem_u32(const void* p) {
    uint32_t r;
    asm("{ .reg .u64 t; cvta.to.shared.u64 t, %1; cvt.u32.u64 %0, t; }"
        : "=r"(r) : "l"(p));
    return r;
}

#define CP_ASYNC16(dst, src) \
    asm volatile("cp.async.cg.shared.global [%0], [%1], 16;" \
                 :: "r"(dst), "l"(src) : "memory")
#define CP_COMMIT() asm volatile("cp.async.commit_group;" ::: "memory")
#define CP_WAIT(N)  asm volatile("cp.async.wait_group %0;" :: "n"(N) : "memory")

#define LDSM_X4(r, addr) \
    asm volatile("ldmatrix.sync.aligned.m8n8.x4.shared.b16 {%0,%1,%2,%3}, [%4];" \
                 : "=r"((r)[0]), "=r"((r)[1]), "=r"((r)[2]), "=r"((r)[3]) \
                 : "r"(addr))

__device__ __forceinline__ void mma8(float* c, const uint32_t* a, const uint32_t* b) {
    asm volatile(
        "mma.sync.aligned.m16n8k8.row.col.f32.tf32.tf32.f32 "
        "{%0,%1,%2,%3}, {%4,%5,%6,%7}, {%8,%9}, {%0,%1,%2,%3};"
        : "+f"(c[0]), "+f"(c[1]), "+f"(c[2]), "+f"(c[3])
        : "r"(a[0]), "r"(a[1]), "r"(a[2]), "r"(a[3]), "r"(b[0]), "r"(b[1]));
}

// ---------------------------------------------------------------- mma GEMM
// C[M,N] = A[M,K] @ B^T, A:[M,K], B:[N,K], all K-major.
// BM=128, BN=128, BK=32; 128 threads = 4 warps (2 M x 2 N), warp tile 64x64.
// 2 CTAs/SM (96KB smem, ~185 regs). 3-stage cp.async pipeline, ONE barrier
// per chunk. Smem tiles [row][32] with XOR swizzle on the float4 column
// (col4' = col4 ^ (row&7)); all fragments via ldmatrix.x4.
// If blockIdx.z == 1, the second operand set (A2/B2/C2/bias2) is used.
// NOTE: MMA reads raw fp32 bits as tf32 (truncation). For exact tf32 math,
// A/B must be pre-rounded to tf32 in gmem (true for Qp, Kp, P, Vt).
// Requires M%128==0, N%128==0, KC=K/32>=2.
template <int EPI>
__global__ void __launch_bounds__(128, 2)
mma_gemm(const float* __restrict__ A, const float* __restrict__ B,
         float* __restrict__ C, const float* __restrict__ bias,
         const int* __restrict__ mask,
         const float* __restrict__ A2, const float* __restrict__ B2,
         float* __restrict__ C2, const float* __restrict__ bias2,
         int M, int N, int K)
{
    constexpr int BM = 128, BN = 128, BK = 32, STAGES = 3;
    constexpr int STAGE_F = (BM + BN) * BK;       // floats per stage (8192)
    constexpr int STAGE_B = STAGE_F * 4;          // bytes (32768)
    constexpr int ABYTES  = BM * BK * 4;          // 16384

    if (blockIdx.z == 1) { A = A2; B = B2; C = C2; bias = bias2; }

    extern __shared__ float sm[];
    const uint32_t smb = smem_u32(sm);

    const int tid  = threadIdx.x;
    const int lane = tid & 31;
    const int wid  = tid >> 5;      // 0..3
    const int g    = lane >> 2;     // group id 0..7
    const int t    = lane & 3;      // thread-in-group 0..3

    const int m_warp = (wid & 1) * 64;   // 2 warps in M
    const int n_warp = (wid >> 1) * 64;  // 2 warps in N

    const int rowBase = blockIdx.y * BM;
    const int colBase = blockIdx.x * BN;

    // ---- ldmatrix per-lane addressing (x4: lane l -> matrix l>>3, row l&7)
    const int mat = lane >> 3;
    const int rim = lane & 7;
    const int km  = mat >> 1;
    const int kb  = mat & 1;
    // A fragment (mi, ks): row = m_warp + 16*mi + rim + 8*kb, col4 = 2*ks + km
    // B fragment (j,  ks): row = n_warp + 16*j  + rim + 8*km, col4 = 2*ks + kb
    const uint32_t aOff = (uint32_t)(m_warp + rim + 8 * kb) * (BK * 4);
    const uint32_t bOff = (uint32_t)ABYTES + (uint32_t)(n_warp + rim + 8 * km) * (BK * 4);

    // loader mapping: rows lr+16*it, float4 col lq, swizzled col sq
    // (16 ≡ 0 mod 8 so (lr+16*it)&7 == lr&7 -> sq constant across it)
    const int lr = tid >> 3;        // 0..15
    const int lq = tid & 7;
    const int sq = lq ^ (lr & 7);

    const float* pa = A + (size_t)(rowBase + lr) * K + lq * 4;
    const float* pb = B + (size_t)(colBase + lr) * K + lq * 4;
    const uint32_t sa = smb + (uint32_t)(lr * BK + 4 * sq) * 4;
    const uint32_t sb = sa + (uint32_t)ABYTES;

    const int KC = K / BK;

    // issue one stage of cp.async (A: 8 x 16B, B: 8 x 16B per thread)
    auto issue = [&](int c, int s) {
        const float* qa = pa + (size_t)c * BK;
        const float* qb = pb + (size_t)c * BK;
        const uint32_t off = (uint32_t)s * STAGE_B;
#pragma unroll
        for (int it = 0; it < 8; it++) {
            CP_ASYNC16(sa + off + (uint32_t)(16 * it * BK) * 4, qa + (size_t)(16 * it) * K);
            CP_ASYNC16(sb + off + (uint32_t)(16 * it * BK) * 4, qb + (size_t)(16 * it) * K);
        }
        CP_COMMIT();
    };

    issue(0, 0);
    issue(1, 1);

    float acc[4][8][4];
#pragma unroll
    for (int i = 0; i < 4; i++)
#pragma unroll
        for (int j = 0; j < 8; j++)
#pragma unroll
            for (int r = 0; r < 4; r++) acc[i][j][r] = 0.0f;

    for (int c = 0; c < KC; c++) {
        if (c + 2 < KC) { CP_WAIT(1); } else { CP_WAIT(0); }
        __syncthreads();
        // all warps passed the barrier => reads of stage (c+2)%3 (iter c-1) done
        if (c + 2 < KC) issue(c + 2, (c + 2) % STAGES);

        const uint32_t stg = smb + (uint32_t)(c % STAGES) * STAGE_B;
#pragma unroll
        for (int ks = 0; ks < 4; ks++) {
            const uint32_t cA = 16u * (uint32_t)((2 * ks + km) ^ rim);
            const uint32_t cB = 16u * (uint32_t)((2 * ks + kb) ^ rim);
            uint32_t af[4][4];
#pragma unroll
            for (int mi = 0; mi < 4; mi++)
                LDSM_X4(af[mi], stg + aOff + (uint32_t)(mi * 16 * BK * 4) + cA);
            uint32_t bf[4][4];   // [j] = {b(n=16j,kLo), b(16j,kHi), b(16j+8,kLo), b(16j+8,kHi)}
#pragma unroll
            for (int j = 0; j < 4; j++)
                LDSM_X4(bf[j], stg + bOff + (uint32_t)(j * 16 * BK * 4) + cB);
#pragma unroll
            for (int mi = 0; mi < 4; mi++)
#pragma unroll
                for (int nj = 0; nj < 8; nj++)
                    mma8(acc[mi][nj], af[mi], &bf[nj >> 1][(nj & 1) * 2]);
        }
    }

    // ---- epilogue
    const int colW = colBase + n_warp;
#pragma unroll
    for (int mi = 0; mi < 4; mi++) {
        const int row0 = rowBase + m_warp + 16 * mi + g;
#pragma unroll
        for (int rr = 0; rr < 2; rr++) {
            const int row = row0 + 8 * rr;
            float* crow = C + (size_t)row * N;
            const int* mrow = (EPI == EPI_MASK) ? (mask + (size_t)row * N) : nullptr;
#pragma unroll
            for (int nj = 0; nj < 8; nj++) {
                const int col = colW + 8 * nj + 2 * t;
                float2 o = make_float2(acc[mi][nj][2 * rr], acc[mi][nj][2 * rr + 1]);
                if (EPI == EPI_BIAS) {
                    const float2 b = *(const float2*)(bias + col);
                    // round to tf32 so downstream cp.async GEMM is exact
                    o.x = f2tf_f(o.x + b.x);
                    o.y = f2tf_f(o.y + b.y);
                } else if (EPI == EPI_MASK) {
                    const int2 m = *(const int2*)(mrow + col);
                    o.x = m.x ? NEGV : o.x * SCALE_P;
                    o.y = m.y ? NEGV : o.y * SCALE_P;
                }
                *(float2*)(crow + col) = o;
            }
        }
    }
}

static constexpr int GEMM_SMEM = 3 * (128 + 128) * 32 * 4;  // 98304 bytes

// ---------------------------------------------------------------- V transpose
// Vt[d][n] = tf32_round(V[n][d]);  V:[NKc][Dc] -> Vt:[Dc][NKc]
__global__ __launch_bounds__(256)
void transpose_kernel(const float* __restrict__ V, float* __restrict__ Vt)
{
    __shared__ float tile[32][33];
    const int d0 = blockIdx.x * 32;
    const int n0 = blockIdx.y * 32;
    const int tx = threadIdx.x, ty = threadIdx.y;
#pragma unroll
    for (int j = 0; j < 32; j += 8)
        tile[ty + j][tx] = V[(size_t)(n0 + ty + j) * Dc + d0 + tx];
    __syncthreads();
#pragma unroll
    for (int j = 0; j < 32; j += 8)
        Vt[(size_t)(d0 + ty + j) * NKc + n0 + tx] = f2tf_f(tile[tx][ty + j]);
}

// ---------------------------------------------------------------- softmax
// In-place row softmax; stores tf32-rounded P so the P@V GEMM is exact.
// float4-vectorized loads/stores, __expf (MUFU) for the exponent.
__global__ __launch_bounds__(256)
void softmax_kernel(float* __restrict__ S)
{
    __shared__ float red[256];
    const int row = blockIdx.x;
    const int t = threadIdx.x;
    float4* p4 = (float4*)(S + (size_t)row * NKc);

    float4 v[8];
    float mx = -3.4e38f;
#pragma unroll
    for (int i = 0; i < 8; i++) {
        v[i] = p4[i * 256 + t];
        mx = fmaxf(mx, fmaxf(fmaxf(v[i].x, v[i].y), fmaxf(v[i].z, v[i].w)));
    }
    red[t] = mx;
    __syncthreads();
    for (int s = 128; s > 0; s >>= 1) {
        if (t < s) red[t] = fmaxf(red[t], red[t + s]);
        __syncthreads();
    }
    mx = red[0];
    __syncthreads();

    float sum = 0.0f;
#pragma unroll
    for (int i = 0; i < 8; i++) {
        v[i].x = __expf(v[i].x - mx);
        v[i].y = __expf(v[i].y - mx);
        v[i].z = __expf(v[i].z - mx);
        v[i].w = __expf(v[i].w - mx);
        sum += (v[i].x + v[i].y) + (v[i].z + v[i].w);
    }
    red[t] = sum;
    __syncthreads();
    for (int s = 128; s > 0; s >>= 1) {
        if (t < s) red[t] += red[t + s];
        __syncthreads();
    }
    const float inv = 1.0f / red[0];
#pragma unroll
    for (int i = 0; i < 8; i++) {
        float4 o;
        o.x = f2tf_f(v[i].x * inv);
        o.y = f2tf_f(v[i].y * inv);
        o.z = f2tf_f(v[i].z * inv);
        o.w = f2tf_f(v[i].w * inv);
        p4[i * 256 + t] = o;
    }
}

// ---------------------------------------------------------------- launcher
extern "C" void kernel_launch(void* const* d_in, const int* in_sizes, int n_in,
                              void* d_out, int out_size)
{
    (void)in_sizes; (void)n_in; (void)out_size;
    const float* Q    = (const float*)d_in[0];
    const float* K    = (const float*)d_in[1];
    const float* V    = (const float*)d_in[2];
    const float* WQw  = (const float*)d_in[3];
    const float* WQb  = (const float*)d_in[4];
    const float* WKw  = (const float*)d_in[5];
    const float* WKb  = (const float*)d_in[6];
    const int*   mask = (const int*)d_in[7];  // numpy bool -> int32 on device
    float* O = (float*)d_out;

    float *Qp, *Kp, *Vt, *S;
    cudaGetSymbolAddress((void**)&Qp, g_Qp);
    cudaGetSymbolAddress((void**)&Kp, g_Kp);
    cudaGetSymbolAddress((void**)&Vt, g_Vt);
    cudaGetSymbolAddress((void**)&S,  g_S);

    cudaFuncSetAttribute(mma_gemm<EPI_BIAS>,
                         cudaFuncAttributeMaxDynamicSharedMemorySize, GEMM_SMEM);
    cudaFuncSetAttribute(mma_gemm<EPI_MASK>,
                         cudaFuncAttributeMaxDynamicSharedMemorySize, GEMM_SMEM);
    cudaFuncSetAttribute(mma_gemm<EPI_NONE>,
                         cudaFuncAttributeMaxDynamicSharedMemorySize, GEMM_SMEM);

    const dim3 blk(128);

    // 0) Vt = tf32(V^T)   [512 x 8192]
    transpose_kernel<<<dim3(Dc / 32, NKc / 32), dim3(32, 8)>>>(V, Vt);

    // 1) Both projections in ONE launch (z=0: Q, z=1: K)   [8192 x 512]
    {
        dim3 grid(Dc / 128, NQc / 128, 2);
        mma_gemm<EPI_BIAS><<<grid, blk, GEMM_SMEM>>>(
            Q, WQw, Qp, WQb, nullptr,
            K, WKw, Kp, WKb, NQc, Dc, Dc);
    }
    // 2) S = mask ? NEG : (Qp @ Kp^T) * (1/sqrt(512))   [8192 x 8192]
    {
        dim3 grid(NKc / 128, NQc / 128, 1);
        mma_gemm<EPI_MASK><<<grid, blk, GEMM_SMEM>>>(
            Qp, Kp, S, nullptr, mask,
            nullptr, nullptr, nullptr, nullptr, NQc, NKc, Dc);
    }
    // 3) P = tf32(softmax_rows(S)), in place
    softmax_kernel<<<NQc, dim3(256)>>>(S);
    // 4) O = P @ V = P @ Vt^T   [8192 x 512]
    {
        dim3 grid(Dc / 128, NQc / 128, 1);
        mma_gemm<EPI_NONE><<<grid, blk, GEMM_SMEM>>>(
            S, Vt, O, nullptr, nullptr,
            nullptr, nullptr, nullptr, nullptr, NQc, Dc, NKc);
    }
}

// round 14
// speedup vs baseline: 1.7811x; 1.0329x over previous
#include <cuda_runtime.h>
#include <cstdint>

// Problem constants (fixed shapes from reference)
#define NQc 8192
#define NKc 8192
#define Dc  512

__device__ __align__(16) float g_Qp[(size_t)NQc * Dc];
__device__ __align__(16) float g_Kp[(size_t)NKc * Dc];
__device__ __align__(16) float g_Vt[(size_t)Dc * NKc];
__device__ __align__(16) float g_S [(size_t)NQc * NKc];

static constexpr float SCALE_P = 0.044194173824159216f; // 1/sqrt(512)
static constexpr float NEGV    = -4294967296.0f;        // -(1<<32)

enum { EPI_NONE = 0, EPI_BIAS = 1, EPI_MASK = 2 };

// fp32 -> tf32 (round-to-nearest) kept in a 32-bit container (low 13 bits zero)
__device__ __forceinline__ uint32_t f2tf(float f) {
    uint32_t r;
    asm("cvt.rna.tf32.f32 %0, %1;" : "=r"(r) : "f"(f));
    return r;
}
__device__ __forceinline__ float f2tf_f(float f) { return __uint_as_float(f2tf(f)); }

__device__ __forceinline__ uint32_t smem_u32(const void* p) {
    uint32_t r;
    asm("{ .reg .u64 t; cvta.to.shared.u64 t, %1; cvt.u32.u64 %0, t; }"
        : "=r"(r) : "l"(p));
    return r;
}

#define CP_ASYNC16(dst, src) \
    asm volatile("cp.async.cg.shared.global [%0], [%1], 16;" \
                 :: "r"(dst), "l"(src) : "memory")
#define CP_COMMIT() asm volatile("cp.async.commit_group;" ::: "memory")
#define CP_WAIT(N)  asm volatile("cp.async.wait_group %0;" :: "n"(N) : "memory")

#define LDSM_X4(r, addr) \
    asm volatile("ldmatrix.sync.aligned.m8n8.x4.shared.b16 {%0,%1,%2,%3}, [%4];" \
                 : "=r"((r)[0]), "=r"((r)[1]), "=r"((r)[2]), "=r"((r)[3]) \
                 : "r"(addr))

__device__ __forceinline__ void mma8(float* c, const uint32_t* a, const uint32_t* b) {
    asm volatile(
        "mma.sync.aligned.m16n8k8.row.col.f32.tf32.tf32.f32 "
        "{%0,%1,%2,%3}, {%4,%5,%6,%7}, {%8,%9}, {%0,%1,%2,%3};"
        : "+f"(c[0]), "+f"(c[1]), "+f"(c[2]), "+f"(c[3])
        : "r"(a[0]), "r"(a[1]), "r"(a[2]), "r"(a[3]), "r"(b[0]), "r"(b[1]));
}

// ---------------------------------------------------------------- mma GEMM
// C[M,N] = A[M,K] @ B^T, A:[M,K], B:[N,K], all K-major.
// BM=128, BN=128, BK=32; 128 threads = 4 warps (2 M x 2 N), warp tile 64x64.
// 2 CTAs/SM (96KB smem). 3-stage cp.async pipeline, ONE barrier per chunk.
// Fragment registers double-buffered: LDSM for k-step ks+1 issued under the
// MMAs of k-step ks (hides the ldmatrix latency at 3 of 4 step boundaries).
// Smem tiles [row][32] with XOR swizzle on the float4 column
// (col4' = col4 ^ (row&7)); all fragments via ldmatrix.x4.
// If blockIdx.z == 1, the second operand set (A2/B2/C2/bias2) is used.
// NOTE: MMA reads raw fp32 bits as tf32 (truncation). For exact tf32 math,
// A/B must be pre-rounded to tf32 in gmem (true for Qp, Kp, P, Vt).
// Requires M%128==0, N%128==0, KC=K/32>=2.
template <int EPI>
__global__ void __launch_bounds__(128, 2)
mma_gemm(const float* __restrict__ A, const float* __restrict__ B,
         float* __restrict__ C, const float* __restrict__ bias,
         const int* __restrict__ mask,
         const float* __restrict__ A2, const float* __restrict__ B2,
         float* __restrict__ C2, const float* __restrict__ bias2,
         int M, int N, int K)
{
    constexpr int BM = 128, BN = 128, BK = 32, STAGES = 3;
    constexpr int STAGE_F = (BM + BN) * BK;       // floats per stage (8192)
    constexpr int STAGE_B = STAGE_F * 4;          // bytes (32768)
    constexpr int ABYTES  = BM * BK * 4;          // 16384

    if (blockIdx.z == 1) { A = A2; B = B2; C = C2; bias = bias2; }

    extern __shared__ float sm[];
    const uint32_t smb = smem_u32(sm);

    const int tid  = threadIdx.x;
    const int lane = tid & 31;
    const int wid  = tid >> 5;      // 0..3
    const int g    = lane >> 2;     // group id 0..7
    const int t    = lane & 3;      // thread-in-group 0..3

    const int m_warp = (wid & 1) * 64;   // 2 warps in M
    const int n_warp = (wid >> 1) * 64;  // 2 warps in N

    const int rowBase = blockIdx.y * BM;
    const int colBase = blockIdx.x * BN;

    // ---- ldmatrix per-lane addressing (x4: lane l -> matrix l>>3, row l&7)
    const int mat = lane >> 3;
    const int rim = lane & 7;
    const int km  = mat >> 1;
    const int kb  = mat & 1;
    // A fragment (mi, ks): row = m_warp + 16*mi + rim + 8*kb, col4 = 2*ks + km
    // B fragment (j,  ks): row = n_warp + 16*j  + rim + 8*km, col4 = 2*ks + kb
    const uint32_t aOff = (uint32_t)(m_warp + rim + 8 * kb) * (BK * 4);
    const uint32_t bOff = (uint32_t)ABYTES + (uint32_t)(n_warp + rim + 8 * km) * (BK * 4);

    // loader mapping: rows lr+16*it, float4 col lq, swizzled col sq
    // (16 ≡ 0 mod 8 so (lr+16*it)&7 == lr&7 -> sq constant across it)
    const int lr = tid >> 3;        // 0..15
    const int lq = tid & 7;
    const int sq = lq ^ (lr & 7);

    const float* pa = A + (size_t)(rowBase + lr) * K + lq * 4;
    const float* pb = B + (size_t)(colBase + lr) * K + lq * 4;
    const uint32_t sa = smb + (uint32_t)(lr * BK + 4 * sq) * 4;
    const uint32_t sb = sa + (uint32_t)ABYTES;

    const int KC = K / BK;

    // issue one stage of cp.async (A: 8 x 16B, B: 8 x 16B per thread)
    auto issue = [&](int c, int s) {
        const float* qa = pa + (size_t)c * BK;
        const float* qb = pb + (size_t)c * BK;
        const uint32_t off = (uint32_t)s * STAGE_B;
#pragma unroll
        for (int it = 0; it < 8; it++) {
            CP_ASYNC16(sa + off + (uint32_t)(16 * it * BK) * 4, qa + (size_t)(16 * it) * K);
            CP_ASYNC16(sb + off + (uint32_t)(16 * it * BK) * 4, qb + (size_t)(16 * it) * K);
        }
        CP_COMMIT();
    };

    issue(0, 0);
    issue(1, 1);

    float acc[4][8][4];
#pragma unroll
    for (int i = 0; i < 4; i++)
#pragma unroll
        for (int j = 0; j < 8; j++)
#pragma unroll
            for (int r = 0; r < 4; r++) acc[i][j][r] = 0.0f;

    uint32_t af[2][4][4];
    uint32_t bf[2][4][4];   // [j] = {b(n=16j,kLo), b(16j,kHi), b(16j+8,kLo), b(16j+8,kHi)}

    // load all fragments of k-step ks from stage base 'stg' into buffer bufi
    auto load_frags = [&](uint32_t stg, int ks, int bufi) {
        const uint32_t cA = 16u * (uint32_t)((2 * ks + km) ^ rim);
        const uint32_t cB = 16u * (uint32_t)((2 * ks + kb) ^ rim);
#pragma unroll
        for (int mi = 0; mi < 4; mi++)
            LDSM_X4(af[bufi][mi], stg + aOff + (uint32_t)(mi * 16 * BK * 4) + cA);
#pragma unroll
        for (int j = 0; j < 4; j++)
            LDSM_X4(bf[bufi][j], stg + bOff + (uint32_t)(j * 16 * BK * 4) + cB);
    };

    for (int c = 0; c < KC; c++) {
        if (c + 2 < KC) { CP_WAIT(1); } else { CP_WAIT(0); }
        __syncthreads();
        // all warps passed the barrier => reads of stage (c+2)%3 (iter c-1) done

        const uint32_t stg = smb + (uint32_t)(c % STAGES) * STAGE_B;
        load_frags(stg, 0, 0);              // prefetch k-step 0

        if (c + 2 < KC) issue(c + 2, (c + 2) % STAGES);

#pragma unroll
        for (int ks = 0; ks < 4; ks++) {
            const int cur = ks & 1;
            if (ks < 3) load_frags(stg, ks + 1, cur ^ 1);
#pragma unroll
            for (int mi = 0; mi < 4; mi++)
#pragma unroll
                for (int nj = 0; nj < 8; nj++)
                    mma8(acc[mi][nj], af[cur][mi], &bf[cur][nj >> 1][(nj & 1) * 2]);
        }
    }

    // ---- epilogue
    const int colW = colBase + n_warp;
#pragma unroll
    for (int mi = 0; mi < 4; mi++) {
        const int row0 = rowBase + m_warp + 16 * mi + g;
#pragma unroll
        for (int rr = 0; rr < 2; rr++) {
            const int row = row0 + 8 * rr;
            float* crow = C + (size_t)row * N;
            const int* mrow = (EPI == EPI_MASK) ? (mask + (size_t)row * N) : nullptr;
#pragma unroll
            for (int nj = 0; nj < 8; nj++) {
                const int col = colW + 8 * nj + 2 * t;
                float2 o = make_float2(acc[mi][nj][2 * rr], acc[mi][nj][2 * rr + 1]);
                if (EPI == EPI_BIAS) {
                    const float2 b = *(const float2*)(bias + col);
                    // round to tf32 so downstream cp.async GEMM is exact
                    o.x = f2tf_f(o.x + b.x);
                    o.y = f2tf_f(o.y + b.y);
                } else if (EPI == EPI_MASK) {
                    const int2 m = *(const int2*)(mrow + col);
                    o.x = m.x ? NEGV : o.x * SCALE_P;
                    o.y = m.y ? NEGV : o.y * SCALE_P;
                }
                *(float2*)(crow + col) = o;
            }
        }
    }
}

static constexpr int GEMM_SMEM = 3 * (128 + 128) * 32 * 4;  // 98304 bytes

// ---------------------------------------------------------------- V transpose
// Vt[d][n] = tf32_round(V[n][d]);  V:[NKc][Dc] -> Vt:[Dc][NKc]
__global__ __launch_bounds__(256)
void transpose_kernel(const float* __restrict__ V, float* __restrict__ Vt)
{
    __shared__ float tile[32][33];
    const int d0 = blockIdx.x * 32;
    const int n0 = blockIdx.y * 32;
    const int tx = threadIdx.x, ty = threadIdx.y;
#pragma unroll
    for (int j = 0; j < 32; j += 8)
        tile[ty + j][tx] = V[(size_t)(n0 + ty + j) * Dc + d0 + tx];
    __syncthreads();
#pragma unroll
    for (int j = 0; j < 32; j += 8)
        Vt[(size_t)(d0 + ty + j) * NKc + n0 + tx] = f2tf_f(tile[tx][ty + j]);
}

// ---------------------------------------------------------------- softmax
// In-place row softmax; stores tf32-rounded P so the P@V GEMM is exact.
// float4-vectorized loads/stores, __expf (MUFU) for the exponent.
__global__ __launch_bounds__(256)
void softmax_kernel(float* __restrict__ S)
{
    __shared__ float red[256];
    const int row = blockIdx.x;
    const int t = threadIdx.x;
    float4* p4 = (float4*)(S + (size_t)row * NKc);

    float4 v[8];
    float mx = -3.4e38f;
#pragma unroll
    for (int i = 0; i < 8; i++) {
        v[i] = p4[i * 256 + t];
        mx = fmaxf(mx, fmaxf(fmaxf(v[i].x, v[i].y), fmaxf(v[i].z, v[i].w)));
    }
    red[t] = mx;
    __syncthreads();
    for (int s = 128; s > 0; s >>= 1) {
        if (t < s) red[t] = fmaxf(red[t], red[t + s]);
        __syncthreads();
    }
    mx = red[0];
    __syncthreads();

    float sum = 0.0f;
#pragma unroll
    for (int i = 0; i < 8; i++) {
        v[i].x = __expf(v[i].x - mx);
        v[i].y = __expf(v[i].y - mx);
        v[i].z = __expf(v[i].z - mx);
        v[i].w = __expf(v[i].w - mx);
        sum += (v[i].x + v[i].y) + (v[i].z + v[i].w);
    }
    red[t] = sum;
    __syncthreads();
    for (int s = 128; s > 0; s >>= 1) {
        if (t < s) red[t] += red[t + s];
        __syncthreads();
    }
    const float inv = 1.0f / red[0];
#pragma unroll
    for (int i = 0; i < 8; i++) {
        float4 o;
        o.x = f2tf_f(v[i].x * inv);
        o.y = f2tf_f(v[i].y * inv);
        o.z = f2tf_f(v[i].z * inv);
        o.w = f2tf_f(v[i].w * inv);
        p4[i * 256 + t] = o;
    }
}

// ---------------------------------------------------------------- launcher
extern "C" void kernel_launch(void* const* d_in, const int* in_sizes, int n_in,
                              void* d_out, int out_size)
{
    (void)in_sizes; (void)n_in; (void)out_size;
    const float* Q    = (const float*)d_in[0];
    const float* K    = (const float*)d_in[1];
    const float* V    = (const float*)d_in[2];
    const float* WQw  = (const float*)d_in[3];
    const float* WQb  = (const float*)d_in[4];
    const float* WKw  = (const float*)d_in[5];
    const float* WKb  = (const float*)d_in[6];
    const int*   mask = (const int*)d_in[7];  // numpy bool -> int32 on device
    float* O = (float*)d_out;

    float *Qp, *Kp, *Vt, *S;
    cudaGetSymbolAddress((void**)&Qp, g_Qp);
    cudaGetSymbolAddress((void**)&Kp, g_Kp);
    cudaGetSymbolAddress((void**)&Vt, g_Vt);
    cudaGetSymbolAddress((void**)&S,  g_S);

    cudaFuncSetAttribute(mma_gemm<EPI_BIAS>,
                         cudaFuncAttributeMaxDynamicSharedMemorySize, GEMM_SMEM);
    cudaFuncSetAttribute(mma_gemm<EPI_MASK>,
                         cudaFuncAttributeMaxDynamicSharedMemorySize, GEMM_SMEM);
    cudaFuncSetAttribute(mma_gemm<EPI_NONE>,
                         cudaFuncAttributeMaxDynamicSharedMemorySize, GEMM_SMEM);

    const dim3 blk(128);

    // 0) Vt = tf32(V^T)   [512 x 8192]
    transpose_kernel<<<dim3(Dc / 32, NKc / 32), dim3(32, 8)>>>(V, Vt);

    // 1) Both projections in ONE launch (z=0: Q, z=1: K)   [8192 x 512]
    {
        dim3 grid(Dc / 128, NQc / 128, 2);
        mma_gemm<EPI_BIAS><<<grid, blk, GEMM_SMEM>>>(
            Q, WQw, Qp, WQb, nullptr,
            K, WKw, Kp, WKb, NQc, Dc, Dc);
    }
    // 2) S = mask ? NEG : (Qp @ Kp^T) * (1/sqrt(512))   [8192 x 8192]
    {
        dim3 grid(NKc / 128, NQc / 128, 1);
        mma_gemm<EPI_MASK><<<grid, blk, GEMM_SMEM>>>(
            Qp, Kp, S, nullptr, mask,
            nullptr, nullptr, nullptr, nullptr, NQc, NKc, Dc);
    }
    // 3) P = tf32(softmax_rows(S)), in place
    softmax_kernel<<<NQc, dim3(256)>>>(S);
    // 4) O = P @ V = P @ Vt^T   [8192 x 512]
    {
        dim3 grid(Dc / 128, NQc / 128, 1);
        mma_gemm<EPI_NONE><<<grid, blk, GEMM_SMEM>>>(
            S, Vt, O, nullptr, nullptr,
            nullptr, nullptr, nullptr, nullptr, NQc, Dc, NKc);
    }
}

// round 15
// speedup vs baseline: 1.9004x; 1.0669x over previous
#include <cuda_runtime.h>
#include <cstdint>

// Problem constants (fixed shapes from reference)
#define NQc 8192
#define NKc 8192
#define Dc  512

__device__ __align__(16) float g_Qp[(size_t)NQc * Dc];
__device__ __align__(16) float g_Kp[(size_t)NKc * Dc];
__device__ __align__(16) float g_Vt[(size_t)Dc * NKc];
__device__ __align__(16) float g_S [(size_t)NQc * NKc];
__device__ __align__(16) float g_Op[(size_t)4 * NQc * Dc];   // split-K partials

static constexpr float SCALE_P = 0.044194173824159216f; // 1/sqrt(512)
static constexpr float NEGV    = -4294967296.0f;        // -(1<<32)

enum { EPI_NONE = 0, EPI_BIAS = 1, EPI_MASK = 2 };
enum { Z_NONE = 0, Z_DUAL = 1, Z_SPLITK = 2 };

// fp32 -> tf32 (round-to-nearest) kept in a 32-bit container (low 13 bits zero)
__device__ __forceinline__ uint32_t f2tf(float f) {
    uint32_t r;
    asm("cvt.rna.tf32.f32 %0, %1;" : "=r"(r) : "f"(f));
    return r;
}
__device__ __forceinline__ float f2tf_f(float f) { return __uint_as_float(f2tf(f)); }

__device__ __forceinline__ uint32_t smem_u32(const void* p) {
    uint32_t r;
    asm("{ .reg .u64 t; cvta.to.shared.u64 t, %1; cvt.u32.u64 %0, t; }"
        : "=r"(r) : "l"(p));
    return r;
}

#define CP_ASYNC16(dst, src) \
    asm volatile("cp.async.cg.shared.global [%0], [%1], 16;" \
                 :: "r"(dst), "l"(src) : "memory")
#define CP_COMMIT() asm volatile("cp.async.commit_group;" ::: "memory")
#define CP_WAIT(N)  asm volatile("cp.async.wait_group %0;" :: "n"(N) : "memory")

#define LDSM_X4(r, addr) \
    asm volatile("ldmatrix.sync.aligned.m8n8.x4.shared.b16 {%0,%1,%2,%3}, [%4];" \
                 : "=r"((r)[0]), "=r"((r)[1]), "=r"((r)[2]), "=r"((r)[3]) \
                 : "r"(addr))

__device__ __forceinline__ void mma8(float* c, const uint32_t* a, const uint32_t* b) {
    asm volatile(
        "mma.sync.aligned.m16n8k8.row.col.f32.tf32.tf32.f32 "
        "{%0,%1,%2,%3}, {%4,%5,%6,%7}, {%8,%9}, {%0,%1,%2,%3};"
        : "+f"(c[0]), "+f"(c[1]), "+f"(c[2]), "+f"(c[3])
        : "r"(a[0]), "r"(a[1]), "r"(a[2]), "r"(a[3]), "r"(b[0]), "r"(b[1]));
}

// ---------------------------------------------------------------- mma GEMM
// C[M,N] = A[M,K_ext] @ B^T, A rows strided KT, B rows strided KT (K-major).
// BM=128, BN=128, BK=32; 128 threads = 4 warps (2 M x 2 N), warp tile 64x64.
// 2 CTAs/SM. 3-stage cp.async pipeline; chunk handoff restructured so the
// next chunk's first fragments are ldmatrix'd right after the barrier
// (zero LDSM latency at chunk start). Fragment regs double-buffered.
// Smem tiles [row][32] with XOR swizzle (col4' = col4 ^ (row&7)).
// ZM == Z_DUAL:   blockIdx.z selects operand set (A2/B2/C2/bias2).
// ZM == Z_SPLITK: blockIdx.z selects K-slice (A/B += z*K, C += z*M*N).
// NOTE: operands must be pre-rounded to tf32 in gmem for exact tf32 math.
// Requires M%128==0, N%128==0, KC=K/32>=2.
template <int EPI, int ZM>
__global__ void __launch_bounds__(128, 2)
mma_gemm(const float* __restrict__ A, const float* __restrict__ B,
         float* __restrict__ C, const float* __restrict__ bias,
         const int* __restrict__ mask,
         const float* __restrict__ A2, const float* __restrict__ B2,
         float* __restrict__ C2, const float* __restrict__ bias2,
         int M, int N, int K, int KT)
{
    constexpr int BM = 128, BN = 128, BK = 32;
    constexpr uint32_t STAGE_B = (BM + BN) * BK * 4;   // 32768 bytes
    constexpr uint32_t ABYTES  = BM * BK * 4;          // 16384

    if (ZM == Z_DUAL && blockIdx.z == 1) { A = A2; B = B2; C = C2; bias = bias2; }
    if (ZM == Z_SPLITK) {
        const size_t z = blockIdx.z;
        A += z * (size_t)K;            // column offset (row stride = KT)
        B += z * (size_t)K;
        C += z * (size_t)M * N;
    }

    extern __shared__ float sm[];
    const uint32_t smb = smem_u32(sm);

    const int tid  = threadIdx.x;
    const int lane = tid & 31;
    const int wid  = tid >> 5;      // 0..3
    const int g    = lane >> 2;     // group id 0..7
    const int t    = lane & 3;      // thread-in-group 0..3

    const int m_warp = (wid & 1) * 64;   // 2 warps in M
    const int n_warp = (wid >> 1) * 64;  // 2 warps in N

    const int rowBase = blockIdx.y * BM;
    const int colBase = blockIdx.x * BN;

    // ---- ldmatrix per-lane addressing (x4: lane l -> matrix l>>3, row l&7)
    const int mat = lane >> 3;
    const int rim = lane & 7;
    const int km  = mat >> 1;
    const int kb  = mat & 1;
    // A fragment (mi, ks): row = m_warp + 16*mi + rim + 8*kb, col4 = 2*ks + km
    // B fragment (j,  ks): row = n_warp + 16*j  + rim + 8*km, col4 = 2*ks + kb
    const uint32_t aOff = (uint32_t)(m_warp + rim + 8 * kb) * (BK * 4);
    const uint32_t bOff = ABYTES + (uint32_t)(n_warp + rim + 8 * km) * (BK * 4);

    // loader mapping: rows lr+16*it, float4 col lq, swizzled col sq
    const int lr = tid >> 3;        // 0..15
    const int lq = tid & 7;
    const int sq = lq ^ (lr & 7);

    const float* pa = A + (size_t)(rowBase + lr) * KT + lq * 4;
    const float* pb = B + (size_t)(colBase + lr) * KT + lq * 4;
    const uint32_t sa = smb + (uint32_t)(lr * BK + 4 * sq) * 4;
    const uint32_t sb = sa + ABYTES;

    const int KC = K / BK;

    // issue one stage of cp.async (A: 8 x 16B, B: 8 x 16B per thread)
    auto issue = [&](int c, uint32_t off) {
        const float* qa = pa + (size_t)c * BK;
        const float* qb = pb + (size_t)c * BK;
#pragma unroll
        for (int it = 0; it < 8; it++) {
            CP_ASYNC16(sa + off + (uint32_t)(16 * it * BK) * 4, qa + (size_t)(16 * it) * KT);
            CP_ASYNC16(sb + off + (uint32_t)(16 * it * BK) * 4, qb + (size_t)(16 * it) * KT);
        }
        CP_COMMIT();
    };

    float acc[4][8][4];
#pragma unroll
    for (int i = 0; i < 4; i++)
#pragma unroll
        for (int j = 0; j < 8; j++)
#pragma unroll
            for (int r = 0; r < 4; r++) acc[i][j][r] = 0.0f;

    uint32_t af[2][4][4];
    uint32_t bf[2][4][4];   // [j] = {b(n=16j,kLo), b(16j,kHi), b(16j+8,kLo), b(16j+8,kHi)}

    auto load_frags = [&](uint32_t stg, int ks, int bufi) {
        const uint32_t cA = 16u * (uint32_t)((2 * ks + km) ^ rim);
        const uint32_t cB = 16u * (uint32_t)((2 * ks + kb) ^ rim);
#pragma unroll
        for (int mi = 0; mi < 4; mi++)
            LDSM_X4(af[bufi][mi], stg + aOff + (uint32_t)(mi * 16 * BK * 4) + cA);
#pragma unroll
        for (int j = 0; j < 4; j++)
            LDSM_X4(bf[bufi][j], stg + bOff + (uint32_t)(j * 16 * BK * 4) + cB);
    };

    // rotating stage offsets: s0 = chunk c, s1 = chunk c+1, s2 = issue target (c+2)
    uint32_t s0 = 0, s1 = STAGE_B, s2 = 2 * STAGE_B;

    // ---- preamble: fill stages 0,1; prefetch chunk0 k-step0 fragments
    issue(0, s0);
    issue(1, s1);
    CP_WAIT(1);                    // oldest group (chunk 0) complete
    __syncthreads();               // visible to all warps
    load_frags(smb + s0, 0, 0);

    for (int c = 0; c < KC; c++) {
        const uint32_t stg = smb + s0;
#pragma unroll
        for (int ks = 0; ks < 4; ks++) {
            const int cur = ks & 1;
            if (ks < 3) load_frags(stg, ks + 1, cur ^ 1);
#pragma unroll
            for (int mi = 0; mi < 4; mi++)
#pragma unroll
                for (int nj = 0; nj < 8; nj++)
                    mma8(acc[mi][nj], af[cur][mi], &bf[cur][nj >> 1][(nj & 1) * 2]);
        }

        if (c + 1 < KC) {
            CP_WAIT(0);            // chunk c+1 resident (my copies)
            __syncthreads();       // all warps' copies visible; closes reads of s2's old data
            load_frags(smb + s1, 0, 0);          // next chunk ks0 — off critical path
            if (c + 2 < KC) issue(c + 2, s2);    // overwrite stage read in iter c-1
            const uint32_t tmp = s0; s0 = s1; s1 = s2; s2 = tmp;
        }
    }

    // ---- epilogue
    const int colW = colBase + n_warp;
#pragma unroll
    for (int mi = 0; mi < 4; mi++) {
        const int row0 = rowBase + m_warp + 16 * mi + g;
#pragma unroll
        for (int rr = 0; rr < 2; rr++) {
            const int row = row0 + 8 * rr;
            float* crow = C + (size_t)row * N;
            const int* mrow = (EPI == EPI_MASK) ? (mask + (size_t)row * N) : nullptr;
#pragma unroll
            for (int nj = 0; nj < 8; nj++) {
                const int col = colW + 8 * nj + 2 * t;
                float2 o = make_float2(acc[mi][nj][2 * rr], acc[mi][nj][2 * rr + 1]);
                if (EPI == EPI_BIAS) {
                    const float2 b = *(const float2*)(bias + col);
                    // round to tf32 so downstream cp.async GEMM is exact
                    o.x = f2tf_f(o.x + b.x);
                    o.y = f2tf_f(o.y + b.y);
                } else if (EPI == EPI_MASK) {
                    const int2 m = *(const int2*)(mrow + col);
                    o.x = m.x ? NEGV : o.x * SCALE_P;
                    o.y = m.y ? NEGV : o.y * SCALE_P;
                }
                *(float2*)(crow + col) = o;
            }
        }
    }
}

static constexpr int GEMM_SMEM = 3 * (128 + 128) * 32 * 4;  // 98304 bytes

// ---------------------------------------------------------------- split-K reduce
// O = sum of 4 partials, each NQc*Dc floats. One float4 per thread.
__global__ __launch_bounds__(256)
void reduce4_kernel(const float* __restrict__ P, float* __restrict__ O)
{
    constexpr size_t S4 = (size_t)NQc * Dc / 4;
    const size_t i = (size_t)blockIdx.x * 256 + threadIdx.x;
    const float4* p = (const float4*)P;
    const float4 a = p[i], b = p[i + S4], c = p[i + 2 * S4], d = p[i + 3 * S4];
    ((float4*)O)[i] = make_float4((a.x + b.x) + (c.x + d.x),
                                  (a.y + b.y) + (c.y + d.y),
                                  (a.z + b.z) + (c.z + d.z),
                                  (a.w + b.w) + (c.w + d.w));
}

// ---------------------------------------------------------------- V transpose
// Vt[d][n] = tf32_round(V[n][d]);  V:[NKc][Dc] -> Vt:[Dc][NKc]
__global__ __launch_bounds__(256)
void transpose_kernel(const float* __restrict__ V, float* __restrict__ Vt)
{
    __shared__ float tile[32][33];
    const int d0 = blockIdx.x * 32;
    const int n0 = blockIdx.y * 32;
    const int tx = threadIdx.x, ty = threadIdx.y;
#pragma unroll
    for (int j = 0; j < 32; j += 8)
        tile[ty + j][tx] = V[(size_t)(n0 + ty + j) * Dc + d0 + tx];
    __syncthreads();
#pragma unroll
    for (int j = 0; j < 32; j += 8)
        Vt[(size_t)(d0 + ty + j) * NKc + n0 + tx] = f2tf_f(tile[tx][ty + j]);
}

// ---------------------------------------------------------------- softmax
// In-place row softmax; stores tf32-rounded P so the P@V GEMM is exact.
// Warp-shuffle reductions: 2 block barriers total.
__global__ __launch_bounds__(256)
void softmax_kernel(float* __restrict__ S)
{
    __shared__ float red[16];
    const int row = blockIdx.x;
    const int t = threadIdx.x;
    const int lane = t & 31, w = t >> 5;
    float4* p4 = (float4*)(S + (size_t)row * NKc);

    float4 v[8];
    float mx = -3.4e38f;
#pragma unroll
    for (int i = 0; i < 8; i++) {
        v[i] = p4[i * 256 + t];
        mx = fmaxf(mx, fmaxf(fmaxf(v[i].x, v[i].y), fmaxf(v[i].z, v[i].w)));
    }
#pragma unroll
    for (int o = 16; o > 0; o >>= 1)
        mx = fmaxf(mx, __shfl_xor_sync(0xFFFFFFFFu, mx, o));
    if (lane == 0) red[w] = mx;
    __syncthreads();
    mx = red[0];
#pragma unroll
    for (int i = 1; i < 8; i++) mx = fmaxf(mx, red[i]);

    float sum = 0.0f;
#pragma unroll
    for (int i = 0; i < 8; i++) {
        v[i].x = __expf(v[i].x - mx);
        v[i].y = __expf(v[i].y - mx);
        v[i].z = __expf(v[i].z - mx);
        v[i].w = __expf(v[i].w - mx);
        sum += (v[i].x + v[i].y) + (v[i].z + v[i].w);
    }
#pragma unroll
    for (int o = 16; o > 0; o >>= 1)
        sum += __shfl_xor_sync(0xFFFFFFFFu, sum, o);
    if (lane == 0) red[8 + w] = sum;
    __syncthreads();
    sum = red[8];
#pragma unroll
    for (int i = 1; i < 8; i++) sum += red[8 + i];

    const float inv = 1.0f / sum;
#pragma unroll
    for (int i = 0; i < 8; i++) {
        float4 o;
        o.x = f2tf_f(v[i].x * inv);
        o.y = f2tf_f(v[i].y * inv);
        o.z = f2tf_f(v[i].z * inv);
        o.w = f2tf_f(v[i].w * inv);
        p4[i * 256 + t] = o;
    }
}

// ---------------------------------------------------------------- launcher
extern "C" void kernel_launch(void* const* d_in, const int* in_sizes, int n_in,
                              void* d_out, int out_size)
{
    (void)in_sizes; (void)n_in; (void)out_size;
    const float* Q    = (const float*)d_in[0];
    const float* K    = (const float*)d_in[1];
    const float* V    = (const float*)d_in[2];
    const float* WQw  = (const float*)d_in[3];
    const float* WQb  = (const float*)d_in[4];
    const float* WKw  = (const float*)d_in[5];
    const float* WKb  = (const float*)d_in[6];
    const int*   mask = (const int*)d_in[7];  // numpy bool -> int32 on device
    float* O = (float*)d_out;

    float *Qp, *Kp, *Vt, *S, *Op;
    cudaGetSymbolAddress((void**)&Qp, g_Qp);
    cudaGetSymbolAddress((void**)&Kp, g_Kp);
    cudaGetSymbolAddress((void**)&Vt, g_Vt);
    cudaGetSymbolAddress((void**)&S,  g_S);
    cudaGetSymbolAddress((void**)&Op, g_Op);

    cudaFuncSetAttribute(mma_gemm<EPI_BIAS, Z_DUAL>,
                         cudaFuncAttributeMaxDynamicSharedMemorySize, GEMM_SMEM);
    cudaFuncSetAttribute(mma_gemm<EPI_MASK, Z_NONE>,
                         cudaFuncAttributeMaxDynamicSharedMemorySize, GEMM_SMEM);
    cudaFuncSetAttribute(mma_gemm<EPI_NONE, Z_SPLITK>,
                         cudaFuncAttributeMaxDynamicSharedMemorySize, GEMM_SMEM);

    const dim3 blk(128);

    // 0) Vt = tf32(V^T)   [512 x 8192]
    transpose_kernel<<<dim3(Dc / 32, NKc / 32), dim3(32, 8)>>>(V, Vt);

    // 1) Both projections in ONE launch (z=0: Q, z=1: K)   [8192 x 512]
    {
        dim3 grid(Dc / 128, NQc / 128, 2);
        mma_gemm<EPI_BIAS, Z_DUAL><<<grid, blk, GEMM_SMEM>>>(
            Q, WQw, Qp, WQb, nullptr,
            K, WKw, Kp, WKb, NQc, Dc, Dc, Dc);
    }
    // 2) S = mask ? NEG : (Qp @ Kp^T) * (1/sqrt(512))   [8192 x 8192]
    {
        dim3 grid(NKc / 128, NQc / 128, 1);
        mma_gemm<EPI_MASK, Z_NONE><<<grid, blk, GEMM_SMEM>>>(
            Qp, Kp, S, nullptr, mask,
            nullptr, nullptr, nullptr, nullptr, NQc, NKc, Dc, Dc);
    }
    // 3) P = tf32(softmax_rows(S)), in place
    softmax_kernel<<<NQc, dim3(256)>>>(S);
    // 4) O = P @ Vt^T via split-K=4 (z = K-slice) + reduction
    {
        dim3 grid(Dc / 128, NQc / 128, 4);
        mma_gemm<EPI_NONE, Z_SPLITK><<<grid, blk, GEMM_SMEM>>>(
            S, Vt, Op, nullptr, nullptr,
            nullptr, nullptr, nullptr, nullptr, NQc, Dc, NKc / 4, NKc);
        reduce4_kernel<<<(NQc * Dc / 4) / 256, 256>>>(Op, O);
    }
}